// round 9
// baseline (speedup 1.0000x reference)
#include <cuda_runtime.h>
#include <math.h>

#define TLEN 512
#define NBATCH 32
#define NT 128              // threads per block
#define MROW 4              // rows (DTW) / cells (HUX) per thread
#define BIGV 1e8f

// Per-batch partials: [0..31]=sum_sq, [32..63]=sum_abs, [64..95]=pcc_b, [96..127]=|dtw_b|
__device__ float g_part[4 * NBATCH];
__device__ unsigned int g_tick;   // zero at load; winner resets each call

__device__ __forceinline__ float ex2(float x) {
    float r; asm("ex2.approx.f32 %0, %1;" : "=f"(r) : "f"(x)); return r;
}
__device__ __forceinline__ float lg2(float x) {
    float r; asm("lg2.approx.f32 %0, %1;" : "=f"(r) : "f"(x)); return r;
}

// softmin, gamma=0.1:  m - 0.1*ln(1 + e^{10(m-mid)} + e^{10(m-M)}), exact min net,
// exp/log base-2 folded (10/ln2, 0.1*ln2). 3 MUFU ops.
__device__ __forceinline__ float softmin3(float a, float b, float c) {
    float lo = fminf(a, b), hi = fmaxf(a, b);
    float m   = fminf(lo, c);
    float mid = fminf(hi, fmaxf(lo, c));
    float M   = fmaxf(hi, c);
    float s = 1.0f + ex2((m - mid) * 14.4269504088896f) + ex2((m - M) * 14.4269504088896f);
    return m - 0.0693147180559945f * lg2(s);
}

__device__ __forceinline__ float block_sum4(float v, float* red) {
    const unsigned full = 0xffffffffu;
#pragma unroll
    for (int o = 16; o > 0; o >>= 1) v += __shfl_down_sync(full, v, o);
    int lane = threadIdx.x & 31;
    int w = threadIdx.x >> 5;
    if (lane == 0) red[w] = v;
    __syncthreads();
    if (w == 0) {
        float t = (lane < 4) ? red[lane] : 0.0f;
        t += __shfl_down_sync(full, t, 2);
        t += __shfl_down_sync(full, t, 1);
        if (lane == 0) red[0] = t;
    }
    __syncthreads();
    float r = red[0];
    __syncthreads();
    return r;
}

__global__ __launch_bounds__(NT, 1)
void seqloss_main(const float* __restrict__ pred_map,
                  const int* __restrict__ lat_idx,
                  const float* __restrict__ omega,
                  const float* __restrict__ omni_ts,
                  float* __restrict__ out)
{
    const int b = blockIdx.x;
    const int t = threadIdx.x;
    const int w = t >> 5;
    const unsigned full = 0xffffffffu;

    __shared__ __align__(16) float sv[2][TLEN];   // HUX double buffer
    __shared__ float  ysh[TLEN];                  // v_out_scaled
    __shared__ float2 dbuf[2][NT + 1];            // neighbor pack {dg, up}, slot 0 = pad
    __shared__ float  red[4];
    __shared__ int    swin;

    // C = dr*omega/dphi ; dr = (215-21.5)*695700/200 = 673089.75 ; dphi = 2pi/512
    const float K = (float)(673089.75 * 512.0 / 6.283185307179586476925287);
    const float C = K * omega[b];

    const int r0 = t * MROW;            // first row / cell of this thread
    const int base = b * TLEN + r0;

    // ---- gather v_in (4 rows per thread) ----
    float c0, c1, c2, c3;
    {
        int l0 = lat_idx[base + 0], l1 = lat_idx[base + 1];
        int l2 = lat_idx[base + 2], l3 = lat_idx[base + 3];
        c0 = pred_map[(base + 0) * 128 + l0];
        c1 = pred_map[(base + 1) * 128 + l1];
        c2 = pred_map[(base + 2) * 128 + l2];
        c3 = pred_map[(base + 3) * 128 + l3];
    }

    // ---- HUX: 200 steps, chunked 4 steps/barrier with 4-cell redundant halo ----
    *(float4*)&sv[0][r0] = make_float4(c0, c1, c2, c3);
    __syncthreads();
    int cur = 0;
#pragma unroll 1
    for (int ph = 0; ph < 50; ++ph) {
        float4 h = (t < NT - 1) ? *(const float4*)&sv[cur][r0 + 4]
                                : *(const float4*)&sv[cur][0];   // periodic wrap
        float wk[8] = {c0, c1, c2, c3, h.x, h.y, h.z, h.w};
#pragma unroll
        for (int s = 0; s < 4; ++s) {
#pragma unroll
            for (int i = 0; i <= 6 - s; ++i) {
                // in-place ascending: wk[i+1] still holds the old value
                wk[i] += __fdividef(C * (wk[i + 1] - wk[i]), fmaxf(wk[i], 1.0f));
            }
        }
        c0 = wk[0]; c1 = wk[1]; c2 = wk[2]; c3 = wk[3];
        *(float4*)&sv[cur ^ 1][r0] = make_float4(c0, c1, c2, c3);
        cur ^= 1;
        __syncthreads();
    }

    // v_out raw
    out[base + 0] = c0; out[base + 1] = c1;
    out[base + 2] = c2; out[base + 3] = c3;

    const float ivs = 1.0f / 1000.0f;
    float vs0 = (c0 - 200.0f) * ivs, vs1 = (c1 - 200.0f) * ivs;
    float vs2 = (c2 - 200.0f) * ivs, vs3 = (c3 - 200.0f) * ivs;
    float x0 = (omni_ts[base + 0] - 200.0f) * ivs;
    float x1 = (omni_ts[base + 1] - 200.0f) * ivs;
    float x2 = (omni_ts[base + 2] - 200.0f) * ivs;
    float x3 = (omni_ts[base + 3] - 200.0f) * ivs;
    *(float4*)&ysh[r0] = make_float4(vs0, vs1, vs2, vs3);
    __syncthreads();

    // ---- per-batch reductions (4 elements per thread, summed locally first) ----
    float d0 = vs0 - x0, d1 = vs1 - x1, d2 = vs2 - x2, d3 = vs3 - x3;
    const float s_sq = block_sum4(d0*d0 + d1*d1 + d2*d2 + d3*d3, red);
    const float s_ab = block_sum4(fabsf(d0) + fabsf(d1) + fabsf(d2) + fabsf(d3), red);
    const float s_v  = block_sum4(vs0 + vs1 + vs2 + vs3, red);
    const float s_o  = block_sum4(x0 + x1 + x2 + x3, red);
    const float vmean = s_v * (1.0f / TLEN);
    const float omean = s_o * (1.0f / TLEN);
    float p0 = vs0 - vmean, p1 = vs1 - vmean, p2 = vs2 - vmean, p3 = vs3 - vmean;
    float q0 = x0 - omean,  q1 = x1 - omean,  q2 = x2 - omean,  q3 = x3 - omean;
    const float s_nt = block_sum4(p0*q0 + p1*q1 + p2*q2 + p3*q3, red);
    const float s_p2 = block_sum4(p0*p0 + p1*p1 + p2*p2 + p3*p3, red);
    const float s_t2 = block_sum4(q0*q0 + q1*q1 + q2*q2 + q3*q3, red);
    const float pcc_b = s_nt / (sqrtf(s_p2) * sqrtf(s_t2));

    if (t == NT - 1) {
        g_part[b]              = s_sq;
        g_part[NBATCH + b]     = s_ab;
        g_part[2 * NBATCH + b] = pcc_b;
    }

    // ---- soft-DTW: 1 diagonal/barrier, 4 rows/thread, 4 warps ----
    // Thread t owns rows r0..r0+3. Registers: curk = R(r0+k, p-1), prevk = R(r0+k, p-2).
    // Neighbor pack dbuf[c][t] = {R(r0-1, p-2), R(r0-1, p-1)} written by thread t-1.
    dbuf[0][t] = make_float2(BIGV, BIGV);
    dbuf[1][t] = make_float2(BIGV, BIGV);
    if (t == NT - 1) {
        dbuf[0][NT] = make_float2(BIGV, BIGV);
        dbuf[1][NT] = make_float2(BIGV, BIGV);
    }
    __syncthreads();

    float dy00 = x0 - ysh[0];
    float cur0 = (t == 0) ? dy00 * dy00 : BIGV;   // R(0,0) on diag p=0
    float cur1 = BIGV, cur2 = BIGV, cur3 = BIGV;
    float prev0 = BIGV, prev1 = BIGV, prev2 = BIGV;

    const int pa_lo = 128 * w;          // warp-active window: p in [pa_lo, pa_lo+638]
    const int pa_hi = 128 * w + 638;

    cur = 0;
#pragma unroll 1
    for (int p = 1; p <= 2 * TLEN - 2; ++p) {
        if (p >= pa_lo && p <= pa_hi) {
            float2 pk = dbuf[cur][t];   // {dg, up} for cell 0
            const int j0 = p - r0;
            float n0 = BIGV, n1 = BIGV, n2 = BIGV, n3 = BIGV;
            // cell 0 (row r0): up=pk.y, left=cur0, dg=pk.x
            if (j0 >= 0 && j0 < TLEN) {
                float dy = x0 - ysh[j0];
                n0 = dy * dy + softmin3(pk.y, cur0, pk.x);
            }
            if (j0 - 1 >= 0 && j0 - 1 < TLEN) {
                float dy = x1 - ysh[j0 - 1];
                n1 = dy * dy + softmin3(cur0, cur1, prev0);
            }
            if (j0 - 2 >= 0 && j0 - 2 < TLEN) {
                float dy = x2 - ysh[j0 - 2];
                n2 = dy * dy + softmin3(cur1, cur2, prev1);
            }
            if (j0 - 3 >= 0 && j0 - 3 < TLEN) {
                float dy = x3 - ysh[j0 - 3];
                n3 = dy * dy + softmin3(cur2, cur3, prev2);
            }
            dbuf[cur ^ 1][t + 1] = make_float2(cur3, n3);
            prev0 = cur0; prev1 = cur1; prev2 = cur2;
            cur0 = n0; cur1 = n1; cur2 = n2; cur3 = n3;
        } else {
            dbuf[cur ^ 1][t + 1] = make_float2(BIGV, BIGV);
        }
        cur ^= 1;
        __syncthreads();
    }
    // thread NT-1's cur3 = R(511, 511)

    if (t == NT - 1) {
        g_part[3 * NBATCH + b] = fabsf(cur3);
        __threadfence();
        unsigned tk = atomicAdd(&g_tick, 1);
        swin = (tk == NBATCH - 1) ? 1 : 0;
    }
    __syncthreads();

    // winner block folds the 4x32 partials into the 4 scalar losses
    if (swin) {
        if (t < 32) {
            float sq  = g_part[t];
            float ab  = g_part[NBATCH + t];
            float pcc = g_part[2 * NBATCH + t];
            float dtw = g_part[3 * NBATCH + t];
#pragma unroll
            for (int o = 16; o > 0; o >>= 1) {
                sq  += __shfl_down_sync(full, sq, o);
                ab  += __shfl_down_sync(full, ab, o);
                pcc += __shfl_down_sync(full, pcc, o);
                dtw += __shfl_down_sync(full, dtw, o);
            }
            if (t == 0) {
                out[NBATCH * TLEN + 0] = ab;                           // mae_loss
                out[NBATCH * TLEN + 1] = 1.0f - pcc * (1.0f / 32.0f);  // pcc_loss
                out[NBATCH * TLEN + 2] = dtw * (1.0f / 32.0f);         // dtw_loss
                out[NBATCH * TLEN + 3] = sqrtf(sq);                    // rmse_loss
            }
        }
        if (t == 64) g_tick = 0;   // re-arm for next graph replay
    }
}

extern "C" void kernel_launch(void* const* d_in, const int* in_sizes, int n_in,
                              void* d_out, int out_size) {
    const float* pred_map = (const float*)d_in[0];
    const int*   lat_idx  = (const int*)d_in[1];
    const float* omega    = (const float*)d_in[2];
    const float* omni_ts  = (const float*)d_in[3];
    float* out = (float*)d_out;

    seqloss_main<<<NBATCH, NT>>>(pred_map, lat_idx, omega, omni_ts, out);
}

// round 10
// speedup vs baseline: 1.3727x; 1.3727x over previous
#include <cuda_runtime.h>
#include <math.h>

#define TLEN 512
#define NBATCH 32
#define BIGV 1e8f

// Per-batch partials: [0..31]=sum_sq, [32..63]=sum_abs, [64..95]=pcc_b, [96..127]=|dtw_b|
__device__ float g_part[4 * NBATCH];
__device__ unsigned int g_tick;   // zero at load; winner resets each call

__device__ __forceinline__ float ex2(float x) {
    float r; asm("ex2.approx.f32 %0, %1;" : "=f"(r) : "f"(x)); return r;
}
__device__ __forceinline__ float lg2(float x) {
    float r; asm("lg2.approx.f32 %0, %1;" : "=f"(r) : "f"(x)); return r;
}

// softmin, gamma=0.1:  m - 0.1*ln(1 + e^{10(m-mid)} + e^{10(m-M)}), exact min net,
// exp/log base-2 folded (10/ln2, 0.1*ln2). 3 MUFU ops.
__device__ __forceinline__ float softmin3(float a, float b, float c) {
    float lo = fminf(a, b), hi = fmaxf(a, b);
    float m   = fminf(lo, c);
    float mid = fminf(hi, fmaxf(lo, c));
    float M   = fmaxf(hi, c);
    float s = 1.0f + ex2((m - mid) * 14.4269504088896f) + ex2((m - M) * 14.4269504088896f);
    return m - 0.0693147180559945f * lg2(s);
}

__device__ __forceinline__ float block_sum(float v, float* red) {
    const unsigned full = 0xffffffffu;
#pragma unroll
    for (int o = 16; o > 0; o >>= 1) v += __shfl_down_sync(full, v, o);
    int lane = threadIdx.x & 31;
    int w = threadIdx.x >> 5;
    if (lane == 0) red[w] = v;
    __syncthreads();
    if (w == 0) {
        float t = (lane < 16) ? red[lane] : 0.0f;
#pragma unroll
        for (int o = 8; o > 0; o >>= 1) t += __shfl_down_sync(full, t, o);
        if (lane == 0) red[0] = t;
    }
    __syncthreads();
    float r = red[0];
    __syncthreads();
    return r;
}

__global__ __launch_bounds__(TLEN, 1)
void seqloss_main(const float* __restrict__ pred_map,
                  const int* __restrict__ lat_idx,
                  const float* __restrict__ omega,
                  const float* __restrict__ omni_ts,
                  float* __restrict__ out)
{
    const int b = blockIdx.x;
    const int t = threadIdx.x;
    const int lane = t & 31;
    const unsigned full = 0xffffffffu;

    __shared__ float  sv[2][TLEN];       // HUX double buffer
    __shared__ float  xsh[TLEN];         // omni_scaled
    __shared__ float  ysh[TLEN];         // v_out_scaled
    __shared__ float2 dbuf[2][TLEN + 1]; // pack {R(i,q-2), R(i,q-1)} at slot i+1; slot 0 = pad
    __shared__ float  red[16];
    __shared__ int    swin;

    // C = dr*omega/dphi ; dr = (215-21.5)*695700/200 = 673089.75 ; dphi = 2pi/512
    const float K = (float)(673089.75 * 512.0 / 6.283185307179586476925287);
    const float C = K * omega[b];

    // ---- gather v_in ----
    const int base = b * TLEN + t;
    const int lat = lat_idx[base];
    float v = pred_map[base * 128 + lat];

    // ---- HUX: 200 steps, 2 steps/barrier with 1 redundant halo divide ----
    sv[0][t] = v;
    __syncthreads();
    int cur = 0;
#pragma unroll 1
    for (int ph = 0; ph < 100; ++ph) {
        float v1 = sv[cur][(t + 1) & (TLEN - 1)];
        float v2 = sv[cur][(t + 2) & (TLEN - 1)];
        float a0 = v  + __fdividef(C * (v1 - v),  fmaxf(v,  1.0f));
        float a1 = v1 + __fdividef(C * (v2 - v1), fmaxf(v1, 1.0f));   // halo (redundant)
        v = a0 + __fdividef(C * (a1 - a0), fmaxf(a0, 1.0f));
        sv[cur ^ 1][t] = v;
        cur ^= 1;
        __syncthreads();
    }

    out[base] = v;

    const float vs = (v - 200.0f) * 0.001f;
    const float xi = (omni_ts[base] - 200.0f) * 0.001f;
    xsh[t] = xi;
    ysh[t] = vs;
    __syncthreads();

    // ---- per-batch reductions ----
    const float diff = vs - xi;
    const float s_sq = block_sum(diff * diff, red);
    const float s_ab = block_sum(fabsf(diff), red);
    const float s_v  = block_sum(vs, red);
    const float s_o  = block_sum(xi, red);
    const float vmean = s_v * (1.0f / TLEN);
    const float omean = s_o * (1.0f / TLEN);
    const float pc = vs - vmean;
    const float tc = xi - omean;
    const float s_nt = block_sum(pc * tc, red);
    const float s_p2 = block_sum(pc * pc, red);
    const float s_t2 = block_sum(tc * tc, red);
    const float pcc_b = s_nt / (sqrtf(s_p2) * sqrtf(s_t2));

    // ---- soft-DTW: 2 diagonals per barrier ----
    // Thread t = row t. Phase ph covers diags q=2ph+1 and q+1.
    // pack = dbuf[c][t] = {R(t-1, q-2), R(t-1, q-1)} (written by thread t-1 last phase).
    // cur0 = R(t, q-1) (own, register).
    // cell(t,q):   rn1 = D + softmin(up=pack.y, left=cur0, dg=pack.x)
    // cell(t,q+1): rn2 = D + softmin(up=nbr rn1 (shfl / lane0 halo), left=rn1, dg=pack.y)
    dbuf[0][t] = make_float2(BIGV, BIGV);
    dbuf[1][t] = make_float2(BIGV, BIGV);
    if (t == TLEN - 1) {
        dbuf[0][TLEN] = make_float2(BIGV, BIGV);
        dbuf[1][TLEN] = make_float2(BIGV, BIGV);
    }
    __syncthreads();
    float d00 = xi - ysh[0];
    d00 = d00 * d00;                       // R(0,0), diag 0
    float cur0 = (t == 0) ? d00 : BIGV;
    if (t == 0) dbuf[0][1] = make_float2(BIGV, d00);
    __syncthreads();
    const float xim1 = (t > 0) ? xsh[t - 1] : 0.0f;

    cur = 0;
#pragma unroll 1
    for (int ph = 0; ph < TLEN - 1; ++ph) {
        const int q = 2 * ph + 1;
        const float2 pk = dbuf[cur][t];
        const int j0 = q - t;
        // diag q
        float rn1 = BIGV;
        if (j0 >= 0 && j0 < TLEN) {
            float dy = xi - ysh[j0];
            rn1 = dy * dy + softmin3(pk.y, cur0, pk.x);
        }
        // halo: lane 0 redundantly computes row t-1's diag-q cell
        float rh = BIGV;
        if (lane == 0 && t > 0) {
            const int jh = j0 + 1;                 // q - (t-1)
            if (jh >= 0 && jh < TLEN) {
                float2 pk2 = dbuf[cur][t - 1];
                float dy = xim1 - ysh[jh];
                rh = dy * dy + softmin3(pk2.y, pk.y, pk2.x);
            }
        }
        // diag q+1
        float up2 = __shfl_up_sync(full, rn1, 1);
        if (lane == 0) up2 = rh;
        const int j2 = j0 + 1;
        float rn2 = BIGV;
        if (j2 >= 0 && j2 < TLEN) {
            float dy = xi - ysh[j2];
            rn2 = dy * dy + softmin3(up2, rn1, pk.y);
        }
        dbuf[cur ^ 1][t + 1] = make_float2(rn1, rn2);
        cur0 = rn2;
        cur ^= 1;
        __syncthreads();
    }
    // thread 511's cur0 = R(511, 511) (diag 1022 = last phase's rn2)

    if (t == TLEN - 1) {
        g_part[b]              = s_sq;
        g_part[NBATCH + b]     = s_ab;
        g_part[2 * NBATCH + b] = pcc_b;
        g_part[3 * NBATCH + b] = fabsf(cur0);
        __threadfence();
        unsigned tk = atomicAdd(&g_tick, 1);
        swin = (tk == NBATCH - 1) ? 1 : 0;
    }
    __syncthreads();

    // winner block folds the 4x32 partials into the 4 scalar losses
    if (swin) {
        if (t < 32) {
            float sq  = g_part[t];
            float ab  = g_part[NBATCH + t];
            float pcc = g_part[2 * NBATCH + t];
            float dtw = g_part[3 * NBATCH + t];
#pragma unroll
            for (int o = 16; o > 0; o >>= 1) {
                sq  += __shfl_down_sync(full, sq, o);
                ab  += __shfl_down_sync(full, ab, o);
                pcc += __shfl_down_sync(full, pcc, o);
                dtw += __shfl_down_sync(full, dtw, o);
            }
            if (t == 0) {
                out[NBATCH * TLEN + 0] = ab;                           // mae_loss
                out[NBATCH * TLEN + 1] = 1.0f - pcc * (1.0f / 32.0f);  // pcc_loss
                out[NBATCH * TLEN + 2] = dtw * (1.0f / 32.0f);         // dtw_loss
                out[NBATCH * TLEN + 3] = sqrtf(sq);                    // rmse_loss
            }
        }
        if (t == 64) g_tick = 0;   // re-arm for next graph replay
    }
}

extern "C" void kernel_launch(void* const* d_in, const int* in_sizes, int n_in,
                              void* d_out, int out_size) {
    const float* pred_map = (const float*)d_in[0];
    const int*   lat_idx  = (const int*)d_in[1];
    const float* omega    = (const float*)d_in[2];
    const float* omni_ts  = (const float*)d_in[3];
    float* out = (float*)d_out;

    seqloss_main<<<NBATCH, TLEN>>>(pred_map, lat_idx, omega, omni_ts, out);
}

// round 13
// speedup vs baseline: 2.6453x; 1.9270x over previous
#include <cuda_runtime.h>
#include <math.h>

#define TLEN 512
#define NBATCH 32
#define BIGV 1e8f

// Per-batch partials: [0..31]=sum_sq, [32..63]=sum_abs, [64..95]=pcc_b, [96..127]=|dtw_b|
__device__ float g_part[4 * NBATCH];
__device__ unsigned int g_tick;   // zero at load; winner resets each call

__device__ __forceinline__ float ex2(float x) {
    float r; asm("ex2.approx.f32 %0, %1;" : "=f"(r) : "f"(x)); return r;
}
__device__ __forceinline__ float lg2(float x) {
    float r; asm("lg2.approx.f32 %0, %1;" : "=f"(r) : "f"(x)); return r;
}

// softmin, gamma=0.1:  m - 0.1*ln(1 + e^{10(m-mid)} + e^{10(m-M)}), exact min net,
// exp/log base-2 folded (10/ln2, 0.1*ln2). 3 MUFU ops, branch-free.
__device__ __forceinline__ float softmin3(float a, float b, float c) {
    float lo = fminf(a, b), hi = fmaxf(a, b);
    float m   = fminf(lo, c);
    float mid = fminf(hi, fmaxf(lo, c));
    float M   = fmaxf(hi, c);
    float s = 1.0f + ex2((m - mid) * 14.4269504088896f) + ex2((m - M) * 14.4269504088896f);
    return m - 0.0693147180559945f * lg2(s);
}

__device__ __forceinline__ float block_sum(float v, float* red) {
    const unsigned full = 0xffffffffu;
#pragma unroll
    for (int o = 16; o > 0; o >>= 1) v += __shfl_down_sync(full, v, o);
    int lane = threadIdx.x & 31;
    int w = threadIdx.x >> 5;
    if (lane == 0) red[w] = v;
    __syncthreads();
    if (w == 0) {
        float t = (lane < 16) ? red[lane] : 0.0f;
#pragma unroll
        for (int o = 8; o > 0; o >>= 1) t += __shfl_down_sync(full, t, o);
        if (lane == 0) red[0] = t;
    }
    __syncthreads();
    float r = red[0];
    __syncthreads();
    return r;
}

__global__ __launch_bounds__(TLEN, 1)
void seqloss_main(const float* __restrict__ pred_map,
                  const int* __restrict__ lat_idx,
                  const float* __restrict__ omega,
                  const float* __restrict__ omni_ts,
                  float* __restrict__ out)
{
    const int b = blockIdx.x;
    const int t = threadIdx.x;
    const unsigned full = 0xffffffffu;

    __shared__ float  sv[2][TLEN];     // HUX double buffer
    __shared__ float  ysh[TLEN];       // v_out_scaled
    __shared__ float2 dA[TLEN + 1];    // diag pack {R(i,p-2), R(i,p-1)} at slot i+1; slot 0 = pad
    __shared__ float2 dB[TLEN + 1];
    __shared__ float  red[16];
    __shared__ int    swin;

    // C = dr*omega/dphi ; dr = (215-21.5)*695700/200 = 673089.75 ; dphi = 2pi/512
    const float K = (float)(673089.75 * 512.0 / 6.283185307179586476925287);
    const float C = K * omega[b];

    // ---- gather v_in ----
    const int base = b * TLEN + t;
    const int lat = lat_idx[base];
    float v = pred_map[base * 128 + lat];

    // ---- HUX: 200 upwind steps, 1 step per barrier (proven R6 form) ----
    sv[0][t] = v;
    __syncthreads();
    int cur = 0;
    for (int k = 0; k < 200; ++k) {
        float vr = sv[cur][(t + 1) & (TLEN - 1)];
        v += __fdividef(C * (vr - v), fmaxf(v, 1.0f));
        sv[cur ^ 1][t] = v;
        cur ^= 1;
        __syncthreads();
    }

    out[base] = v;

    const float vs = (v - 200.0f) * 0.001f;
    const float xi = (omni_ts[base] - 200.0f) * 0.001f;   // omni_scaled, own row
    ysh[t] = vs;
    __syncthreads();

    // ---- per-batch reductions ----
    const float diff = vs - xi;
    const float s_sq = block_sum(diff * diff, red);
    const float s_ab = block_sum(fabsf(diff), red);
    const float s_v  = block_sum(vs, red);
    const float s_o  = block_sum(xi, red);
    const float vmean = s_v * (1.0f / TLEN);
    const float omean = s_o * (1.0f / TLEN);
    const float pc = vs - vmean;
    const float tc = xi - omean;
    const float s_nt = block_sum(pc * tc, red);
    const float s_p2 = block_sum(pc * pc, red);
    const float s_t2 = block_sum(tc * tc, red);
    const float pcc_b = s_nt / (sqrtf(s_p2) * sqrtf(s_t2));

    // ---- soft-DTW wavefront: branch-free, 1 diag/barrier, LDS.64 + register 'left' ----
    // Out-of-band cells compute rn = d + (BIGV-ish softmin); fp32 absorption pins
    // them at exactly 1e8 (ulp=8 there), so they behave as the BIG padding the
    // algorithm requires. No predication, no BSSY/BSYNC in the loop.
    dA[t] = make_float2(BIGV, BIGV);
    dB[t] = make_float2(BIGV, BIGV);
    if (t == TLEN - 1) {
        dA[TLEN] = make_float2(BIGV, BIGV);
        dB[TLEN] = make_float2(BIGV, BIGV);
    }
    __syncthreads();
    float d00 = xi - ysh[0];
    d00 = d00 * d00;                        // R(0,0) on diag 0
    float left = (t == 0) ? d00 : BIGV;     // own value on previous diagonal
    if (t == 0) dA[1] = make_float2(BIGV, d00);
    __syncthreads();

    int j = 1 - t;
#pragma unroll 1
    for (int ph = 0; ph < TLEN - 1; ++ph) {
        // step A (diag p = 2ph+1): read dA, write dB
        {
            float2 nb = dA[t];                       // {dg, up} from row t-1
            int jc = min(max(j, 0), TLEN - 1);
            float dy = xi - ysh[jc];
            float rn = dy * dy + softmin3(nb.y, left, nb.x);
            dB[t + 1] = make_float2(left, rn);
            left = rn;
            ++j;
        }
        __syncthreads();
        // step B (diag p = 2ph+2): read dB, write dA
        {
            float2 nb = dB[t];
            int jc = min(max(j, 0), TLEN - 1);
            float dy = xi - ysh[jc];
            float rn = dy * dy + softmin3(nb.y, left, nb.x);
            dA[t + 1] = make_float2(left, rn);
            left = rn;
            ++j;
        }
        __syncthreads();
    }
    // 2*(TLEN-1) = 1022 steps done; thread 511's 'left' = R(511, 511).

    if (t == TLEN - 1) {
        g_part[b]              = s_sq;
        g_part[NBATCH + b]     = s_ab;
        g_part[2 * NBATCH + b] = pcc_b;
        g_part[3 * NBATCH + b] = fabsf(left);
        __threadfence();
        unsigned tk = atomicAdd(&g_tick, 1);
        swin = (tk == NBATCH - 1) ? 1 : 0;
    }
    __syncthreads();

    // last block folds the 4x32 partials into the 4 scalar losses
    if (swin) {
        if (t < 32) {
            float sq  = g_part[t];
            float ab  = g_part[NBATCH + t];
            float pcc = g_part[2 * NBATCH + t];
            float dtw = g_part[3 * NBATCH + t];
#pragma unroll
            for (int o = 16; o > 0; o >>= 1) {
                sq  += __shfl_down_sync(full, sq, o);
                ab  += __shfl_down_sync(full, ab, o);
                pcc += __shfl_down_sync(full, pcc, o);
                dtw += __shfl_down_sync(full, dtw, o);
            }
            if (t == 0) {
                out[NBATCH * TLEN + 0] = ab;                           // mae_loss
                out[NBATCH * TLEN + 1] = 1.0f - pcc * (1.0f / 32.0f);  // pcc_loss
                out[NBATCH * TLEN + 2] = dtw * (1.0f / 32.0f);         // dtw_loss
                out[NBATCH * TLEN + 3] = sqrtf(sq);                    // rmse_loss
            }
        }
        if (t == 64) g_tick = 0;   // re-arm for next graph replay
    }
}

extern "C" void kernel_launch(void* const* d_in, const int* in_sizes, int n_in,
                              void* d_out, int out_size) {
    const float* pred_map = (const float*)d_in[0];
    const int*   lat_idx  = (const int*)d_in[1];
    const float* omega    = (const float*)d_in[2];
    const float* omni_ts  = (const float*)d_in[3];
    float* out = (float*)d_out;

    seqloss_main<<<NBATCH, TLEN>>>(pred_map, lat_idx, omega, omni_ts, out);
}

// round 14
// speedup vs baseline: 2.7959x; 1.0570x over previous
#include <cuda_runtime.h>
#include <math.h>

#define TLEN 512
#define NT 256            // threads per block; thread t owns rows/cells 2t, 2t+1
#define NBATCH 32
#define BIGV 1e8f

// Per-batch partials: [0..31]=sum_sq, [32..63]=sum_abs, [64..95]=pcc_b, [96..127]=|dtw_b|
__device__ float g_part[4 * NBATCH];
__device__ unsigned int g_tick;   // zero at load; winner resets each call

__device__ __forceinline__ float ex2(float x) {
    float r; asm("ex2.approx.f32 %0, %1;" : "=f"(r) : "f"(x)); return r;
}
__device__ __forceinline__ float lg2(float x) {
    float r; asm("lg2.approx.f32 %0, %1;" : "=f"(r) : "f"(x)); return r;
}

// softmin, gamma=0.1:  m - 0.1*ln(1 + e^{10(m-mid)} + e^{10(m-M)}), exact min net,
// exp/log base-2 folded (10/ln2, 0.1*ln2). 3 MUFU ops, branch-free.
__device__ __forceinline__ float softmin3(float a, float b, float c) {
    float lo = fminf(a, b), hi = fmaxf(a, b);
    float m   = fminf(lo, c);
    float mid = fminf(hi, fmaxf(lo, c));
    float M   = fmaxf(hi, c);
    float s = 1.0f + ex2((m - mid) * 14.4269504088896f) + ex2((m - M) * 14.4269504088896f);
    return m - 0.0693147180559945f * lg2(s);
}

__device__ __forceinline__ float block_sum8(float v, float* red) {
    const unsigned full = 0xffffffffu;
#pragma unroll
    for (int o = 16; o > 0; o >>= 1) v += __shfl_down_sync(full, v, o);
    int lane = threadIdx.x & 31;
    int w = threadIdx.x >> 5;
    if (lane == 0) red[w] = v;
    __syncthreads();
    if (w == 0) {
        float t = (lane < 8) ? red[lane] : 0.0f;
        t += __shfl_down_sync(full, t, 4);
        t += __shfl_down_sync(full, t, 2);
        t += __shfl_down_sync(full, t, 1);
        if (lane == 0) red[0] = t;
    }
    __syncthreads();
    float r = red[0];
    __syncthreads();
    return r;
}

__global__ __launch_bounds__(NT, 1)
void seqloss_main(const float* __restrict__ pred_map,
                  const int* __restrict__ lat_idx,
                  const float* __restrict__ omega,
                  const float* __restrict__ omni_ts,
                  float* __restrict__ out)
{
    const int b = blockIdx.x;
    const int t = threadIdx.x;
    const int w = t >> 5;
    const unsigned full = 0xffffffffu;

    __shared__ float2 sv[2][NT];             // HUX double buffer, {c0,c1} per thread
    __shared__ __align__(8) float ysh[TLEN]; // v_out_scaled
    __shared__ float4 dA[NT + 1];            // pack {(2t+1,j0-1),(2t+1,j0),(2t+1,j0+1),-} at slot t+1
    __shared__ float4 dB[NT + 1];
    __shared__ float red[8];
    __shared__ int   swin;

    // C = dr*omega/dphi ; dr = (215-21.5)*695700/200 = 673089.75 ; dphi = 2pi/512
    const float K = (float)(673089.75 * 512.0 / 6.283185307179586476925287);
    const float C = K * omega[b];

    const int base = b * TLEN + 2 * t;

    // ---- gather v_in (2 cells) ----
    const int l0 = lat_idx[base];
    const int l1 = lat_idx[base + 1];
    float c0 = pred_map[base * 128 + l0];
    float c1 = pred_map[(base + 1) * 128 + l1];

    // ---- HUX: 200 steps, 1 barrier/step, 2 cells/thread (independent divides) ----
    sv[0][t] = make_float2(c0, c1);
    __syncthreads();
    int cur = 0;
    for (int k = 0; k < 200; ++k) {
        float vn = sv[cur][(t + 1) & (NT - 1)].x;   // right neighbor of cell 2t+1
        float n0 = c0 + __fdividef(C * (c1 - c0), fmaxf(c0, 1.0f));
        float n1 = c1 + __fdividef(C * (vn - c1), fmaxf(c1, 1.0f));
        c0 = n0; c1 = n1;
        sv[cur ^ 1][t] = make_float2(c0, c1);
        cur ^= 1;
        __syncthreads();
    }

    out[base]     = c0;
    out[base + 1] = c1;

    const float vs0 = (c0 - 200.0f) * 0.001f;
    const float vs1 = (c1 - 200.0f) * 0.001f;
    const float x0  = (omni_ts[base]     - 200.0f) * 0.001f;   // omni rows 2t, 2t+1
    const float x1  = (omni_ts[base + 1] - 200.0f) * 0.001f;
    *(float2*)&ysh[2 * t] = make_float2(vs0, vs1);
    __syncthreads();

    // ---- per-batch reductions (2 elems/thread) ----
    const float d0 = vs0 - x0, d1 = vs1 - x1;
    const float s_sq = block_sum8(d0 * d0 + d1 * d1, red);
    const float s_ab = block_sum8(fabsf(d0) + fabsf(d1), red);
    const float s_v  = block_sum8(vs0 + vs1, red);
    const float s_o  = block_sum8(x0 + x1, red);
    const float vmean = s_v * (1.0f / TLEN);
    const float omean = s_o * (1.0f / TLEN);
    const float p0 = vs0 - vmean, p1 = vs1 - vmean;
    const float q0 = x0 - omean,  q1 = x1 - omean;
    const float s_nt = block_sum8(p0 * q0 + p1 * q1, red);
    const float s_p2 = block_sum8(p0 * p0 + p1 * p1, red);
    const float s_t2 = block_sum8(q0 * q0 + q1 * q1, red);
    const float pcc_b = s_nt / (sqrtf(s_p2) * sqrtf(s_t2));

    // ---- soft-DTW: 2x2 cells/thread, 2 diagonals per barrier, 511 steps ----
    // Step s: thread t computes rows 2t,2t+1 at columns j0=2s-2t, j0+1.
    //   c00=(2t,j0):    up=pk.y, left=c01p (own, s-1), diag=pk.x
    //   c01=(2t,j0+1):  up=pk.z, left=c00,             diag=pk.y
    //   c10=(2t+1,j0):  up=c00,  left=c11p (own, s-1), diag=c01p
    //   c11=(2t+1,j0+1):up=c01,  left=c10,             diag=c00
    // pack written = {c11p, c10, c11} = row 2t+1 at cols j0-1, j0, j0+1 (for thread t+1).
    // Out-of-band cells clamp j and are pinned to exactly 1e8 by fp32 absorption.
    dA[t] = make_float4(BIGV, BIGV, BIGV, 0.0f);
    dB[t] = make_float4(BIGV, BIGV, BIGV, 0.0f);
    if (t == NT - 1) {
        dA[NT] = make_float4(BIGV, BIGV, BIGV, 0.0f);
        dB[NT] = make_float4(BIGV, BIGV, BIGV, 0.0f);
    }
    __syncthreads();

    float c01p = BIGV, c11p = BIGV;
    float4 *X = dA, *Y = dB;
    const int slo = 32 * w;          // warp active window [slo, slo+287]
    const int shi = 32 * w + 287;

#pragma unroll 1
    for (int s = 0; s <= 2 * (NT - 1); ++s) {   // s = 0..510
        if (s >= slo && s <= shi) {
            float4 pk = X[t];
            int j0 = 2 * s - 2 * t;
            int jc = min(max(j0, 0), TLEN - 2);
            float2 y2 = *(const float2*)&ysh[jc];
            float dy;
            dy = x0 - y2.x; float dsq = dy * dy;
            float c00 = dsq + softmin3(pk.y, c01p, pk.x);
            c00 = ((s | t) == 0) ? dsq : c00;            // seed R(0,0) = D(0,0)
            dy = x0 - y2.y; float c01 = dy * dy + softmin3(pk.z, c00, pk.y);
            dy = x1 - y2.x; float c10 = dy * dy + softmin3(c00, c11p, c01p);
            dy = x1 - y2.y; float c11 = dy * dy + softmin3(c01, c10, c00);
            Y[t + 1] = make_float4(c11p, c10, c11, 0.0f);
            c01p = c01; c11p = c11;
        }
        __syncthreads();
        float4* tmp = X; X = Y; Y = tmp;
    }
    // thread 255: c11p = R(511, 511) (its c11 at s = 510)

    if (t == NT - 1) {
        g_part[b]              = s_sq;
        g_part[NBATCH + b]     = s_ab;
        g_part[2 * NBATCH + b] = pcc_b;
        g_part[3 * NBATCH + b] = fabsf(c11p);
        __threadfence();
        unsigned tk = atomicAdd(&g_tick, 1);
        swin = (tk == NBATCH - 1) ? 1 : 0;
    }
    __syncthreads();

    // last block folds the 4x32 partials into the 4 scalar losses
    if (swin) {
        if (t < 32) {
            float sq  = g_part[t];
            float ab  = g_part[NBATCH + t];
            float pcc = g_part[2 * NBATCH + t];
            float dtw = g_part[3 * NBATCH + t];
#pragma unroll
            for (int o = 16; o > 0; o >>= 1) {
                sq  += __shfl_down_sync(full, sq, o);
                ab  += __shfl_down_sync(full, ab, o);
                pcc += __shfl_down_sync(full, pcc, o);
                dtw += __shfl_down_sync(full, dtw, o);
            }
            if (t == 0) {
                out[NBATCH * TLEN + 0] = ab;                           // mae_loss
                out[NBATCH * TLEN + 1] = 1.0f - pcc * (1.0f / 32.0f);  // pcc_loss
                out[NBATCH * TLEN + 2] = dtw * (1.0f / 32.0f);         // dtw_loss
                out[NBATCH * TLEN + 3] = sqrtf(sq);                    // rmse_loss
            }
        }
        if (t == 64) g_tick = 0;   // re-arm for next graph replay
    }
}

extern "C" void kernel_launch(void* const* d_in, const int* in_sizes, int n_in,
                              void* d_out, int out_size) {
    const float* pred_map = (const float*)d_in[0];
    const int*   lat_idx  = (const int*)d_in[1];
    const float* omega    = (const float*)d_in[2];
    const float* omni_ts  = (const float*)d_in[3];
    float* out = (float*)d_out;

    seqloss_main<<<NBATCH, NT>>>(pred_map, lat_idx, omega, omni_ts, out);
}